// round 1
// baseline (speedup 1.0000x reference)
#include <cuda_runtime.h>

#define WDIM 1024
#define NPIX (WDIM * WDIM)

static __device__ __forceinline__ unsigned long long pack2(float a, float b) {
    unsigned long long r;
    asm("mov.b64 %0, {%1,%2};" : "=l"(r) : "f"(a), "f"(b));
    return r;
}
static __device__ __forceinline__ void fma2(unsigned long long& d, unsigned long long a, unsigned long long b) {
    asm("fma.rn.f32x2 %0, %1, %2, %0;" : "+l"(d) : "l"(a), "l"(b));
}
static __device__ __forceinline__ float2 unpack2(unsigned long long v) {
    float2 r;
    asm("mov.b64 {%0,%1}, %2;" : "=f"(r.x), "=f"(r.y) : "l"(v));
    return r;
}

__global__ void __launch_bounds__(256) energy_cnn_kernel(
    const float* __restrict__ se, const float* __restrict__ te,
    const float* __restrict__ sr, const float* __restrict__ hc,
    const float* __restrict__ rot, const float* __restrict__ w1,
    const float* __restrict__ b1, const float* __restrict__ w2,
    const float* __restrict__ b2, float* __restrict__ out)
{
    // w1s[(c*9+j)*32 + o] = w1[o][c][j]   (w1 global layout: (32,6,3,3))
    __shared__ __align__(16) float w1s[54 * 32];
    // w2s[o*16 + m] = w2[m][o] (m<13), zero-padded to 16 output channels
    __shared__ __align__(16) float w2s[32 * 16];

    const int tid = threadIdx.x;
    for (int i = tid; i < 54 * 32; i += 256) {
        int cj = i >> 5, o = i & 31;
        w1s[i] = w1[o * 54 + cj];
    }
    for (int i = tid; i < 32 * 16; i += 256) {
        int o = i >> 4, m = i & 15;
        w2s[i] = (m < 13) ? w2[m * 32 + o] : 0.0f;
    }
    __syncthreads();

    const int p = blockIdx.x * 256 + tid;
    const int x = p & (WDIM - 1);
    const int y = p >> 10;

    // direction: replicate jax math exactly: (ang / 2pi) * 4 -> int32 -> %4
    const float TP = 6.2831853071795864f;
    float ang = rot[p];                 // inputs are uniform[0,1)*2pi, so mod 2pi is identity
    float t = ang / TP * 4.0f;
    int d = ((int)t) & 3;
    const int rb0 = d & 1;              // 90-degree step
    const int rb1 = (d >> 1) & 1;       // 180-degree step

    // Rotated neighbor addresses + output-channel slot per gather j.
    // rotated[j] = patch at offset R^d(dy0,dx0), where one 90-deg step maps (dy,dx)->(-dx,dy).
    int idx[9];
    int kq[9];
#pragma unroll
    for (int j = 0; j < 9; j++) {
        const int dy0 = j / 3 - 1, dx0 = j % 3 - 1;
        int ay = rb1 ? -dy0 : dy0;
        int ax = rb1 ? -dx0 : dx0;
        int dy = rb0 ? -ax : ay;
        int dx = rb0 ? ay : ax;
        int yy = (y + dy) & (WDIM - 1);
        int xx = (x + dx) & (WDIM - 1);
        idx[j] = (yy << 10) + xx;
        kq[j] = (dy + 1) * 3 + (dx + 1);   // = ROT[d][j], the inverse-rotated output slot
    }

    // ---- layer 1: 54 -> 32, packed over output-channel pairs ----
    unsigned long long acc[16];
#pragma unroll
    for (int i = 0; i < 16; i++)
        acc[i] = pack2(__ldg(&b1[2 * i]), __ldg(&b1[2 * i + 1]));

    const float* chans[6] = { se, te, sr, hc, hc + NPIX, hc + 2 * NPIX };
#pragma unroll
    for (int c = 0; c < 6; c++) {
        const float* __restrict__ ch = chans[c];
        float a[9];
#pragma unroll
        for (int j = 0; j < 9; j++) a[j] = __ldg(&ch[idx[j]]);
#pragma unroll
        for (int j = 0; j < 9; j++) {
            unsigned long long aa = pack2(a[j], a[j]);
            const ulonglong2* __restrict__ wrow =
                (const ulonglong2*)&w1s[(c * 9 + j) * 32];
#pragma unroll
            for (int i = 0; i < 8; i++) {
                ulonglong2 wv = wrow[i];
                fma2(acc[2 * i], aa, wv.x);
                fma2(acc[2 * i + 1], aa, wv.y);
            }
        }
    }

    float h[32];
#pragma unroll
    for (int i = 0; i < 16; i++) {
        float2 v = unpack2(acc[i]);
        h[2 * i]     = fmaxf(v.x, 0.0f);
        h[2 * i + 1] = fmaxf(v.y, 0.0f);
    }

    // ---- layer 2: 32 -> 13 (padded to 16), packed over output pairs ----
    unsigned long long x2[8];
#pragma unroll
    for (int m = 0; m < 8; m++) {
        float ba = (2 * m < 13)     ? __ldg(&b2[2 * m])     : 0.0f;
        float bb = (2 * m + 1 < 13) ? __ldg(&b2[2 * m + 1]) : 0.0f;
        x2[m] = pack2(ba, bb);
    }
#pragma unroll
    for (int o = 0; o < 32; o++) {
        unsigned long long hh = pack2(h[o], h[o]);
        const ulonglong2* __restrict__ wq = (const ulonglong2*)&w2s[o * 16];
#pragma unroll
        for (int m = 0; m < 4; m++) {
            ulonglong2 wv = wq[m];
            fma2(x2[2 * m], hh, wv.x);
            fma2(x2[2 * m + 1], hh, wv.y);
        }
    }

    float z[16];
#pragma unroll
    for (int m = 0; m < 8; m++) {
        float2 v = unpack2(x2[m]);
        z[2 * m] = v.x; z[2 * m + 1] = v.y;
    }

    // softmax over z[0..8]
    float mx = z[0];
#pragma unroll
    for (int j = 1; j < 9; j++) mx = fmaxf(mx, z[j]);
    float s[9];
    float sum = 0.0f;
#pragma unroll
    for (int j = 0; j < 9; j++) { s[j] = __expf(z[j] - mx); sum += s[j]; }
    float inv = __fdividef(1.0f, sum);

    // inverse rotation is free: props_back[ROT[d][j]] = softmax[j], ROT[d][j] == kq[j]
#pragma unroll
    for (int j = 0; j < 9; j++)
        out[kq[j] * NPIX + p] = s[j] * inv;

    out[9 * NPIX + p] = tanhf(z[9]);
#pragma unroll
    for (int m = 0; m < 3; m++) {
        float v = z[10 + m];
        out[(10 + m) * NPIX + p] = __fdividef(1.0f, 1.0f + __expf(-v));
    }
}

extern "C" void kernel_launch(void* const* d_in, const int* in_sizes, int n_in,
                              void* d_out, int out_size)
{
    const float* se  = (const float*)d_in[0];   // shareable_energy (W,W)
    const float* te  = (const float*)d_in[1];   // terrain          (W,W)
    const float* sr  = (const float*)d_in[2];   // sharing_rate     (W,W)
    const float* hc  = (const float*)d_in[3];   // hidden_channels  (3,W,W)
    const float* rot = (const float*)d_in[4];   // rotation_matrix  (W,W)
    const float* w1  = (const float*)d_in[5];   // (32,6,3,3)
    const float* b1  = (const float*)d_in[6];   // (32,)
    const float* w2  = (const float*)d_in[7];   // (13,32)
    const float* b2  = (const float*)d_in[8];   // (13,)
    float* out = (float*)d_out;                 // 13*N floats: props(9N) | share(N) | hidden(3N)

    energy_cnn_kernel<<<NPIX / 256, 256>>>(se, te, sr, hc, rot, w1, b1, w2, b2, out);
}

// round 2
// speedup vs baseline: 1.6251x; 1.6251x over previous
#include <cuda_runtime.h>

#define WDIM 1024
#define NPIX (WDIM * WDIM)
#define HALF (NPIX / 2)

static __device__ __forceinline__ unsigned long long pack2(float a, float b) {
    unsigned long long r;
    asm("mov.b64 %0, {%1,%2};" : "=l"(r) : "f"(a), "f"(b));
    return r;
}
static __device__ __forceinline__ void fma2(unsigned long long& d, unsigned long long a, unsigned long long b) {
    asm("fma.rn.f32x2 %0, %1, %2, %0;" : "+l"(d) : "l"(a), "l"(b));
}
static __device__ __forceinline__ float2 unpack2(unsigned long long v) {
    float2 r;
    asm("mov.b64 {%0,%1}, %2;" : "=f"(r.x), "=f"(r.y) : "l"(v));
    return r;
}

// Per-pixel epilogue: softmax(9) + inverse rotation (pure register selects) +
// tanh + sigmoid. All stores fully coalesced (plane index is compile-time).
static __device__ __forceinline__ void epilogue(const float* z, int d, int p,
                                                float* __restrict__ out)
{
    const int rb0 = d & 1;
    const int rb1 = (d >> 1) & 1;

    float mx = z[0];
#pragma unroll
    for (int j = 1; j < 9; j++) mx = fmaxf(mx, z[j]);
    float s[9];
    float sum = 0.0f;
#pragma unroll
    for (int j = 0; j < 9; j++) { s[j] = __expf(z[j] - mx); sum += s[j]; }
    float inv = __fdividef(1.0f, sum);

    // s_back[m] = s[IROT[d][m]]  (compile-time index tables -> 3 SELs per m)
    const int I0[9] = {0,1,2,3,4,5,6,7,8};
    const int I1[9] = {2,5,8,1,4,7,0,3,6};
    const int I2[9] = {8,7,6,5,4,3,2,1,0};
    const int I3[9] = {6,3,0,7,4,1,8,5,2};
#pragma unroll
    for (int m = 0; m < 9; m++) {
        float v01 = rb0 ? s[I1[m]] : s[I0[m]];
        float v23 = rb0 ? s[I3[m]] : s[I2[m]];
        float v = rb1 ? v23 : v01;
        out[m * NPIX + p] = v * inv;
    }
    out[9 * NPIX + p] = tanhf(z[9]);
#pragma unroll
    for (int m = 0; m < 3; m++)
        out[(10 + m) * NPIX + p] = __fdividef(1.0f, 1.0f + __expf(-z[10 + m]));
}

__global__ void __launch_bounds__(256, 2) energy_cnn_kernel(
    const float* __restrict__ se, const float* __restrict__ te,
    const float* __restrict__ sr, const float* __restrict__ hc,
    const float* __restrict__ rot, const float* __restrict__ w1,
    const float* __restrict__ b1, const float* __restrict__ w2,
    const float* __restrict__ b2, float* __restrict__ out)
{
    // w1s[(c*9+j)*32 + o] = w1[o][c][j]   (w1 global layout: (32,6,3,3))
    __shared__ __align__(16) float w1s[54 * 32];
    // w2s[o*16 + m] = w2[m][o] (m<13), zero-padded to 16 output channels
    __shared__ __align__(16) float w2s[32 * 16];
    __shared__ __align__(16) unsigned long long b1p[16];
    __shared__ __align__(16) unsigned long long b2p[8];

    const int tid = threadIdx.x;
    for (int i = tid; i < 54 * 32; i += 256) {
        int cj = i >> 5, o = i & 31;
        w1s[i] = w1[o * 54 + cj];
    }
    for (int i = tid; i < 32 * 16; i += 256) {
        int o = i >> 4, m = i & 15;
        w2s[i] = (m < 13) ? w2[m * 32 + o] : 0.0f;
    }
    if (tid < 16) b1p[tid] = pack2(b1[2 * tid], b1[2 * tid + 1]);
    if (tid < 8) {
        float ba = (2 * tid < 13)     ? b2[2 * tid]     : 0.0f;
        float bb = (2 * tid + 1 < 13) ? b2[2 * tid + 1] : 0.0f;
        b2p[tid] = pack2(ba, bb);
    }
    __syncthreads();

    // Two pixels per thread: p0 in the top half, p1 = p0 + HALF.
    const int p0 = blockIdx.x * 256 + tid;
    const int p1 = p0 + HALF;
    const int x0 = p0 & (WDIM - 1), y0 = p0 >> 10;
    const int x1 = x0,              y1 = y0 + (WDIM / 2);

    const float TP = 6.2831853071795864f;
    int d0, d1;
    {
        float t = rot[p0] / TP * 4.0f;  d0 = ((int)t) & 3;
        float u = rot[p1] / TP * 4.0f;  d1 = ((int)u) & 3;
    }

    // Rotated gather addresses (rotation = address permutation).
    int idx0[9], idx1[9];
    {
        const int rb00 = d0 & 1, rb01 = (d0 >> 1) & 1;
        const int rb10 = d1 & 1, rb11 = (d1 >> 1) & 1;
#pragma unroll
        for (int j = 0; j < 9; j++) {
            const int dy0 = j / 3 - 1, dx0 = j % 3 - 1;
            {
                int ay = rb01 ? -dy0 : dy0;
                int ax = rb01 ? -dx0 : dx0;
                int dy = rb00 ? -ax : ay;
                int dx = rb00 ? ay : ax;
                idx0[j] = (((y0 + dy) & (WDIM - 1)) << 10) + ((x0 + dx) & (WDIM - 1));
            }
            {
                int ay = rb11 ? -dy0 : dy0;
                int ax = rb11 ? -dx0 : dx0;
                int dy = rb10 ? -ax : ay;
                int dx = rb10 ? ay : ax;
                idx1[j] = (((y1 + dy) & (WDIM - 1)) << 10) + ((x1 + dx) & (WDIM - 1));
            }
        }
    }

    // ---- layer 1: 54 -> 32, output-channel-pair packed, 2 pixels share weights ----
    unsigned long long acc0[16], acc1[16];
#pragma unroll
    for (int i = 0; i < 16; i++) { acc0[i] = b1p[i]; acc1[i] = b1p[i]; }

    const float* chans[6] = { se, te, sr, hc, hc + NPIX, hc + 2 * NPIX };
#pragma unroll
    for (int c = 0; c < 6; c++) {
        const float* __restrict__ ch = chans[c];
#pragma unroll
        for (int j = 0; j < 9; j++) {
            float a0 = __ldg(&ch[idx0[j]]);
            float a1 = __ldg(&ch[idx1[j]]);
            unsigned long long aa0 = pack2(a0, a0);
            unsigned long long aa1 = pack2(a1, a1);
            const ulonglong2* __restrict__ wrow =
                (const ulonglong2*)&w1s[(c * 9 + j) * 32];
#pragma unroll
            for (int i = 0; i < 8; i++) {
                ulonglong2 wv = wrow[i];
                fma2(acc0[2 * i],     aa0, wv.x);
                fma2(acc0[2 * i + 1], aa0, wv.y);
                fma2(acc1[2 * i],     aa1, wv.x);
                fma2(acc1[2 * i + 1], aa1, wv.y);
            }
        }
    }

    float h0[32], h1[32];
#pragma unroll
    for (int i = 0; i < 16; i++) {
        float2 v0 = unpack2(acc0[i]);
        float2 v1 = unpack2(acc1[i]);
        h0[2 * i]     = fmaxf(v0.x, 0.0f);
        h0[2 * i + 1] = fmaxf(v0.y, 0.0f);
        h1[2 * i]     = fmaxf(v1.x, 0.0f);
        h1[2 * i + 1] = fmaxf(v1.y, 0.0f);
    }

    // ---- layer 2: 32 -> 13 (padded 16), 2 pixels share weights ----
    unsigned long long x20[8], x21[8];
#pragma unroll
    for (int m = 0; m < 8; m++) { x20[m] = b2p[m]; x21[m] = b2p[m]; }
#pragma unroll
    for (int o = 0; o < 32; o++) {
        unsigned long long hh0 = pack2(h0[o], h0[o]);
        unsigned long long hh1 = pack2(h1[o], h1[o]);
        const ulonglong2* __restrict__ wq = (const ulonglong2*)&w2s[o * 16];
#pragma unroll
        for (int m = 0; m < 4; m++) {
            ulonglong2 wv = wq[m];
            fma2(x20[2 * m],     hh0, wv.x);
            fma2(x20[2 * m + 1], hh0, wv.y);
            fma2(x21[2 * m],     hh1, wv.x);
            fma2(x21[2 * m + 1], hh1, wv.y);
        }
    }

    float z0[14], z1[14];
#pragma unroll
    for (int m = 0; m < 7; m++) {
        float2 v0 = unpack2(x20[m]);
        float2 v1 = unpack2(x21[m]);
        z0[2 * m] = v0.x; z0[2 * m + 1] = v0.y;
        z1[2 * m] = v1.x; z1[2 * m + 1] = v1.y;
    }

    epilogue(z0, d0, p0, out);
    epilogue(z1, d1, p1, out);
}

extern "C" void kernel_launch(void* const* d_in, const int* in_sizes, int n_in,
                              void* d_out, int out_size)
{
    const float* se  = (const float*)d_in[0];
    const float* te  = (const float*)d_in[1];
    const float* sr  = (const float*)d_in[2];
    const float* hc  = (const float*)d_in[3];
    const float* rot = (const float*)d_in[4];
    const float* w1  = (const float*)d_in[5];
    const float* b1  = (const float*)d_in[6];
    const float* w2  = (const float*)d_in[7];
    const float* b2  = (const float*)d_in[8];
    float* out = (float*)d_out;

    energy_cnn_kernel<<<HALF / 256, 256>>>(se, te, sr, hc, rot, w1, b1, w2, b2, out);
}